// round 5
// baseline (speedup 1.0000x reference)
#include <cuda_runtime.h>
#include <cuda_bf16.h>
#include <math.h>

// ---------------------------------------------------------------------------
// Problem constants
// ---------------------------------------------------------------------------
#define NF   128          // frames
#define PP   576          // patches
#define DD   1536         // feature dim
#define LM   4096
#define NQ   64
#define PG   9            // patches per pool group (576/64)
#define NM1  127          // N-1
#define NCUBES 8

#define OUT_GATE 0
#define OUT_TH   254
#define OUT_Z    (254 + NQ * LM)   // 262398
// total out = 262526

// ---------------------------------------------------------------------------
// Scratch (static __device__ arrays; no allocation)
// ---------------------------------------------------------------------------
__device__ float g_framepool[(size_t)NF * NQ * DD];   // per-frame per-group patch sums (50 MB)
__device__ float g_framemean[NF * DD];
__device__ float g_mommean[NF * DD];                  // rows 0..126 used
__device__ float g_feat[NF * DD];
__device__ float g_xn[NF * DD];
__device__ float g_h[NF * DD];
__device__ float g_pooled[NQ * DD];
__device__ float g_part[4 * NQ * LM];                 // split-K partials (max 4*64*4096 = 4 MB)
__device__ float g_y[NM1];
__device__ int   g_selidx[PG];
__device__ float g_selw[PG];
__device__ float g_scale;

// ---------------------------------------------------------------------------
// K1: stream video_features once -> framepool[n][g][d] = sum of 9 patches
// grid (64, 128), 384 threads, float4 per thread
// ---------------------------------------------------------------------------
__global__ void __launch_bounds__(384) pool_kernel(const float* __restrict__ vf) {
    int g = blockIdx.x;
    int n = blockIdx.y;
    int d4 = threadIdx.x;                 // 0..383 (x4 floats = 1536)
    const float4* base = (const float4*)(vf + ((size_t)n * PP + (size_t)g * PG) * DD);
    float4 s = make_float4(0.f, 0.f, 0.f, 0.f);
#pragma unroll
    for (int r = 0; r < PG; r++) {
        float4 v = base[(size_t)r * (DD / 4) + d4];
        s.x += v.x; s.y += v.y; s.z += v.z; s.w += v.w;
    }
    float4* dst = (float4*)(g_framepool + ((size_t)n * NQ + g) * DD);
    dst[d4] = s;
}

// ---------------------------------------------------------------------------
// K2: framemean[n][d] = sum_g framepool[n][g][d] / 576
// ---------------------------------------------------------------------------
__global__ void __launch_bounds__(384) mean_kernel() {
    int n = blockIdx.x;
    int d4 = threadIdx.x;
    const float4* src = (const float4*)(g_framepool + (size_t)n * NQ * DD);
    float4 s = make_float4(0.f, 0.f, 0.f, 0.f);
#pragma unroll 8
    for (int g = 0; g < NQ; g++) {
        float4 v = src[(size_t)g * (DD / 4) + d4];
        s.x += v.x; s.y += v.y; s.z += v.z; s.w += v.w;
    }
    const float inv = 1.0f / (float)PP;
    s.x *= inv; s.y *= inv; s.z *= inv; s.w *= inv;
    ((float4*)(g_framemean + n * DD))[d4] = s;
}

// ---------------------------------------------------------------------------
// K3: momentum EMA scan over frame-diffs of framemean
// mom[0] = fm[1]-fm[0]; mom[i] = 0.5*(fm[i+1]-fm[i]) + 0.5*mom[i-1]
// ---------------------------------------------------------------------------
__global__ void scan_kernel() {
    int d = blockIdx.x * blockDim.x + threadIdx.x;
    if (d >= DD) return;
    float fm_prev = g_framemean[d];
    float fm_cur  = g_framemean[DD + d];
    float m = fm_cur - fm_prev;
    g_mommean[d] = m;
    for (int i = 1; i < NM1; i++) {
        fm_prev = fm_cur;
        fm_cur = g_framemean[(i + 1) * DD + d];
        float diff = fm_cur - fm_prev;
        m = 0.5f * diff + 0.5f * m;
        g_mommean[i * DD + d] = m;
    }
}

// ---------------------------------------------------------------------------
// Split-K fp32 GEMM: part[z] = A[M,K-chunk] @ B[K-chunk,N]
// BM=32, BN=128, BK=32, 256 threads, 4x4 microtile, deterministic partials.
// ---------------------------------------------------------------------------
#define BM 32
#define BN 128
#define BK 32
__global__ void __launch_bounds__(256) gemm_splitk(
    const float* __restrict__ A, const float* __restrict__ B,
    float* __restrict__ Cpart, int M, int N, int K)
{
    __shared__ float As[BK][BM];
    __shared__ float Bs[BK][BN];
    int tid = threadIdx.x;
    int n0 = blockIdx.x * BN;
    int m0 = blockIdx.y * BM;
    int splitk = gridDim.z;
    int kchunk = K / splitk;
    int k0 = blockIdx.z * kchunk;
    int ksteps = kchunk / BK;

    int ty = tid >> 5;            // 0..7 -> rows ty*4..ty*4+3
    int tx = tid & 31;            // 0..31 -> cols tx*4..tx*4+3
    int a_m = tid >> 3;           // 0..31
    int a_k = (tid & 7) * 4;      // 0..28
    int b_r = tid >> 5;           // 0..7
    int b_c = (tid & 31) * 4;     // 0..124

    float acc[4][4] = {};

    for (int kt = 0; kt < ksteps; kt++) {
        int kbase = k0 + kt * BK;
        // load A tile (guard M)
        float4 av = make_float4(0.f, 0.f, 0.f, 0.f);
        int mg = m0 + a_m;
        if (mg < M) av = *(const float4*)&A[(size_t)mg * K + kbase + a_k];
        As[a_k + 0][a_m] = av.x;
        As[a_k + 1][a_m] = av.y;
        As[a_k + 2][a_m] = av.z;
        As[a_k + 3][a_m] = av.w;
        // load B tile
#pragma unroll
        for (int j = 0; j < 4; j++) {
            int kr = b_r + j * 8;
            *(float4*)&Bs[kr][b_c] =
                *(const float4*)&B[(size_t)(kbase + kr) * N + n0 + b_c];
        }
        __syncthreads();
#pragma unroll
        for (int kk = 0; kk < BK; kk++) {
            float4 a = *(const float4*)&As[kk][ty * 4];
            float4 b = *(const float4*)&Bs[kk][tx * 4];
            float ar[4] = {a.x, a.y, a.z, a.w};
            float br[4] = {b.x, b.y, b.z, b.w};
#pragma unroll
            for (int i = 0; i < 4; i++)
#pragma unroll
                for (int j = 0; j < 4; j++)
                    acc[i][j] = fmaf(ar[i], br[j], acc[i][j]);
        }
        __syncthreads();
    }

    size_t MN = (size_t)M * N;
    float* base = Cpart + (size_t)blockIdx.z * MN;
#pragma unroll
    for (int i = 0; i < 4; i++) {
        int mg = m0 + ty * 4 + i;
        if (mg < M) {
            float4 v = make_float4(acc[i][0], acc[i][1], acc[i][2], acc[i][3]);
            *(float4*)&base[(size_t)mg * N + n0 + tx * 4] = v;
        }
    }
}

// ---------------------------------------------------------------------------
// Combine split-K partials + bias (+ optional exact GELU)
// ---------------------------------------------------------------------------
__global__ void combine_kernel(const float* __restrict__ part,
                               const float* __restrict__ bias,
                               float* __restrict__ dst,
                               int M, int N, int splitk, int do_gelu)
{
    int idx = blockIdx.x * blockDim.x + threadIdx.x;
    int total = M * N;
    if (idx >= total) return;
    float v = bias[idx % N];
    size_t MN = (size_t)total;
    for (int z = 0; z < splitk; z++) v += part[(size_t)z * MN + idx];
    if (do_gelu) v = 0.5f * v * (1.0f + erff(v * 0.70710678118654752f));
    dst[idx] = v;
}

// ---------------------------------------------------------------------------
// LayerNorm over feat rows -> xn
// ---------------------------------------------------------------------------
__global__ void __launch_bounds__(256) ln_kernel(const float* __restrict__ ln_g,
                                                 const float* __restrict__ ln_b)
{
    int row = blockIdx.x;
    const float* x = g_feat + row * DD;
    float s = 0.f, ss = 0.f;
    for (int d = threadIdx.x; d < DD; d += 256) {
        float v = x[d];
        s += v;
        ss = fmaf(v, v, ss);
    }
    __shared__ float sh1[8], sh2[8];
    int lane = threadIdx.x & 31, w = threadIdx.x >> 5;
#pragma unroll
    for (int o = 16; o; o >>= 1) {
        s  += __shfl_xor_sync(0xFFFFFFFFu, s, o);
        ss += __shfl_xor_sync(0xFFFFFFFFu, ss, o);
    }
    if (lane == 0) { sh1[w] = s; sh2[w] = ss; }
    __syncthreads();
    if (w == 0) {
        s  = (lane < 8) ? sh1[lane] : 0.f;
        ss = (lane < 8) ? sh2[lane] : 0.f;
#pragma unroll
        for (int o = 4; o; o >>= 1) {
            s  += __shfl_xor_sync(0xFFFFFFFFu, s, o);
            ss += __shfl_xor_sync(0xFFFFFFFFu, ss, o);
        }
        if (lane == 0) { sh1[0] = s; sh2[0] = ss; }
    }
    __syncthreads();
    float mu  = sh1[0] * (1.0f / DD);
    float var = sh2[0] * (1.0f / DD) - mu * mu;
    float rstd = rsqrtf(var + 1e-5f);
    for (int d = threadIdx.x; d < DD; d += 256)
        g_xn[row * DD + d] = (x[d] - mu) * rstd * ln_g[d] + ln_b[d];
}

// ---------------------------------------------------------------------------
// Gate head: gate_logits = h @ W2 + b2 ; y = softmax((logits + g*0.1)/0.5)[1]
// grid 127, 64 threads (warp w handles output column w)
// ---------------------------------------------------------------------------
__global__ void __launch_bounds__(64) gate_kernel(const float* __restrict__ W2,
                                                  const float* __restrict__ b2,
                                                  const float* __restrict__ gu,
                                                  float* __restrict__ out)
{
    int row = blockIdx.x;
    int w = threadIdx.x >> 5, lane = threadIdx.x & 31;
    const float* hrow = g_h + row * DD;
    float s = 0.f;
    for (int d = lane; d < DD; d += 32)
        s = fmaf(hrow[d], W2[d * 2 + w], s);
#pragma unroll
    for (int o = 16; o; o >>= 1) s += __shfl_xor_sync(0xFFFFFFFFu, s, o);
    __shared__ float sl[2];
    if (lane == 0) sl[w] = s + b2[w];
    __syncthreads();
    if (threadIdx.x == 0) {
        float l0 = sl[0], l1 = sl[1];
        out[OUT_GATE + row * 2 + 0] = l0;
        out[OUT_GATE + row * 2 + 1] = l1;
        float u0 = gu[row * 2 + 0], u1 = gu[row * 2 + 1];
        float g0 = -logf(-logf(u0 + 1e-20f) + 1e-20f);
        float g1 = -logf(-logf(u1 + 1e-20f) + 1e-20f);
        float a0 = (l0 + g0 * 0.1f) * 2.0f;   // / TEMP(0.5)
        float a1 = (l1 + g1 * 0.1f) * 2.0f;
        float mx = fmaxf(a0, a1);
        float e0 = expf(a0 - mx), e1 = expf(a1 - mx);
        g_y[row] = e1 / (e0 + e1);
    }
}

// ---------------------------------------------------------------------------
// Top-8 selection (stable: max value, lowest index on ties), z_hard, weights
// ---------------------------------------------------------------------------
__global__ void __launch_bounds__(128) topk_kernel(float* __restrict__ out) {
    __shared__ float yv[128];
    __shared__ float rv[128];
    __shared__ int   ri[128];
    __shared__ int   taken[128];
    int t = threadIdx.x;
    yv[t] = (t < NM1) ? g_y[t] : -1e30f;
    taken[t] = 0;
    __syncthreads();
    for (int it = 0; it < NCUBES; it++) {
        rv[t] = taken[t] ? -1e30f : yv[t];
        ri[t] = t;
        __syncthreads();
        for (int off = 64; off > 0; off >>= 1) {
            if (t < off) {
                float v2 = rv[t + off]; int i2 = ri[t + off];
                if (v2 > rv[t] || (v2 == rv[t] && i2 < ri[t])) { rv[t] = v2; ri[t] = i2; }
            }
            __syncthreads();
        }
        if (t == 0) taken[ri[0]] = 1;
        __syncthreads();
    }
    // z_hard output (forward value of straight-through)
    float z = 0.f;
    if (t < NM1) z = taken[t] ? ((1.0f - yv[t]) + yv[t]) : 0.0f;
    if (t == 0) out[OUT_Z] = 1.0f;
    if (t < NM1) out[OUT_Z + 1 + t] = z;
    // sum z
    rv[t] = z;
    __syncthreads();
    for (int off = 64; off > 0; off >>= 1) {
        if (t < off) rv[t] += rv[t + off];
        __syncthreads();
    }
    if (t == 0) {
        float zsum = 1.0f + rv[0];
        g_scale = 1.0f / ((float)PG * zsum);
        g_selidx[0] = 0; g_selw[0] = 1.0f;
        int c = 1;
        for (int i = 0; i < NM1; i++) {
            if (taken[i]) {
                g_selidx[c] = i + 1;
                g_selw[c] = (1.0f - yv[i]) + yv[i];
                c++;
            }
        }
    }
}

// ---------------------------------------------------------------------------
// pooled[g][d] = scale * sum_k w_k * framepool[sel_k][g][d]
// ---------------------------------------------------------------------------
__global__ void __launch_bounds__(384) pooled_kernel() {
    int g = blockIdx.x;
    int d4 = threadIdx.x;
    float4 acc = make_float4(0.f, 0.f, 0.f, 0.f);
#pragma unroll
    for (int k = 0; k < PG; k++) {
        int n = g_selidx[k];
        float w = g_selw[k];
        float4 v = ((const float4*)(g_framepool + ((size_t)n * NQ + g) * DD))[d4];
        acc.x = fmaf(w, v.x, acc.x);
        acc.y = fmaf(w, v.y, acc.y);
        acc.z = fmaf(w, v.z, acc.z);
        acc.w = fmaf(w, v.w, acc.w);
    }
    float sc = g_scale;
    acc.x *= sc; acc.y *= sc; acc.z *= sc; acc.w *= sc;
    ((float4*)(g_pooled + g * DD))[d4] = acc;
}

// ---------------------------------------------------------------------------
// launch
// ---------------------------------------------------------------------------
extern "C" void kernel_launch(void* const* d_in, const int* in_sizes, int n_in,
                              void* d_out, int out_size) {
    const float* vf    = (const float*)d_in[0];
    const float* gu    = (const float*)d_in[1];
    const float* W_agg = (const float*)d_in[2];
    const float* b_agg = (const float*)d_in[3];
    const float* ln_g  = (const float*)d_in[4];
    const float* ln_b  = (const float*)d_in[5];
    const float* W1    = (const float*)d_in[6];
    const float* b1    = (const float*)d_in[7];
    const float* W2    = (const float*)d_in[8];
    const float* b2    = (const float*)d_in[9];
    const float* W_th  = (const float*)d_in[10];
    const float* b_th  = (const float*)d_in[11];
    float* out = (float*)d_out;

    float* d_part;   cudaGetSymbolAddress((void**)&d_part,   g_part);
    float* d_mom;    cudaGetSymbolAddress((void**)&d_mom,    g_mommean);
    float* d_feat;   cudaGetSymbolAddress((void**)&d_feat,   g_feat);
    float* d_xn;     cudaGetSymbolAddress((void**)&d_xn,     g_xn);
    float* d_h;      cudaGetSymbolAddress((void**)&d_h,      g_h);
    float* d_pooled; cudaGetSymbolAddress((void**)&d_pooled, g_pooled);

    // 1) stream video features once
    pool_kernel<<<dim3(NQ, NF), 384>>>(vf);
    // 2) frame means
    mean_kernel<<<NF, 384>>>();
    // 3) momentum EMA scan
    scan_kernel<<<4, 384>>>();
    // 4) feat = mommean @ W_agg + b_agg   (split-K=4)
    gemm_splitk<<<dim3(DD / BN, (NM1 + BM - 1) / BM, 4), 256>>>(d_mom, W_agg, d_part, NM1, DD, DD);
    combine_kernel<<<(NM1 * DD + 255) / 256, 256>>>(d_part, b_agg, d_feat, NM1, DD, 4, 0);
    // 5) LayerNorm
    ln_kernel<<<NM1, 256>>>(ln_g, ln_b);
    // 6) h = gelu(xn @ W1 + b1)
    gemm_splitk<<<dim3(DD / BN, (NM1 + BM - 1) / BM, 4), 256>>>(d_xn, W1, d_part, NM1, DD, DD);
    combine_kernel<<<(NM1 * DD + 255) / 256, 256>>>(d_part, b1, d_h, NM1, DD, 4, 1);
    // 7) gate logits + gumbel softmax y
    gate_kernel<<<NM1, 64>>>(W2, b2, gu, out);
    // 8) top-8 + z_hard
    topk_kernel<<<1, 128>>>(out);
    // 9) pooled from framepool (selected frames only)
    pooled_kernel<<<NQ, 384>>>();
    // 10) thumbnail = pooled @ W_th + b_th
    gemm_splitk<<<dim3(LM / BN, NQ / BM, 4), 256>>>(d_pooled, W_th, d_part, NQ, LM, DD);
    combine_kernel<<<(NQ * LM + 255) / 256, 256>>>(d_part, b_th, out + OUT_TH, NQ, LM, 4, 0);
}

// round 6
// speedup vs baseline: 1.0031x; 1.0031x over previous
#include <cuda_runtime.h>
#include <cuda_bf16.h>
#include <math.h>

// ---------------------------------------------------------------------------
// Problem constants
// ---------------------------------------------------------------------------
#define NF   128          // frames
#define PP   576          // patches
#define DD   1536         // feature dim
#define LM   4096
#define NQ   64
#define PG   9            // patches per pool group (576/64)
#define NM1  127          // N-1
#define NCUBES 8

#define OUT_GATE 0
#define OUT_TH   254
#define OUT_Z    (254 + NQ * LM)   // 262398
// total out = 262526

// ---------------------------------------------------------------------------
// Scratch (static __device__ arrays; no allocation)
// ---------------------------------------------------------------------------
__device__ float g_framepool[(size_t)NF * NQ * DD];   // per-frame per-group patch sums (50 MB)
__device__ float g_framemean[NF * DD];
__device__ float g_mommean[NF * DD];                  // rows 0..126 used
__device__ float g_feat[NF * DD];
__device__ float g_xn[NF * DD];
__device__ float g_h[NF * DD];
__device__ float g_pooled[NQ * DD];
__device__ float g_part[4 * NQ * LM];                 // split-K partials (max 4*64*4096 = 4 MB)
__device__ float g_y[NM1];
__device__ int   g_selidx[PG];
__device__ float g_selw[PG];
__device__ float g_scale;

// ---------------------------------------------------------------------------
// K1: stream video_features once -> framepool[n][g][d] = sum of 9 patches
// grid (64, 128), 384 threads, float4 per thread
// ---------------------------------------------------------------------------
__global__ void __launch_bounds__(384) pool_kernel(const float* __restrict__ vf) {
    int g = blockIdx.x;
    int n = blockIdx.y;
    int d4 = threadIdx.x;                 // 0..383 (x4 floats = 1536)
    const float4* base = (const float4*)(vf + ((size_t)n * PP + (size_t)g * PG) * DD);
    float4 s = make_float4(0.f, 0.f, 0.f, 0.f);
#pragma unroll
    for (int r = 0; r < PG; r++) {
        float4 v = base[(size_t)r * (DD / 4) + d4];
        s.x += v.x; s.y += v.y; s.z += v.z; s.w += v.w;
    }
    float4* dst = (float4*)(g_framepool + ((size_t)n * NQ + g) * DD);
    dst[d4] = s;
}

// ---------------------------------------------------------------------------
// K2: framemean[n][d] = sum_g framepool[n][g][d] / 576
// ---------------------------------------------------------------------------
__global__ void __launch_bounds__(384) mean_kernel() {
    int n = blockIdx.x;
    int d4 = threadIdx.x;
    const float4* src = (const float4*)(g_framepool + (size_t)n * NQ * DD);
    float4 s = make_float4(0.f, 0.f, 0.f, 0.f);
#pragma unroll 8
    for (int g = 0; g < NQ; g++) {
        float4 v = src[(size_t)g * (DD / 4) + d4];
        s.x += v.x; s.y += v.y; s.z += v.z; s.w += v.w;
    }
    const float inv = 1.0f / (float)PP;
    s.x *= inv; s.y *= inv; s.z *= inv; s.w *= inv;
    ((float4*)(g_framemean + n * DD))[d4] = s;
}

// ---------------------------------------------------------------------------
// K3: momentum EMA scan over frame-diffs of framemean
// mom[0] = fm[1]-fm[0]; mom[i] = 0.5*(fm[i+1]-fm[i]) + 0.5*mom[i-1]
// ---------------------------------------------------------------------------
__global__ void scan_kernel() {
    int d = blockIdx.x * blockDim.x + threadIdx.x;
    if (d >= DD) return;
    float fm_prev = g_framemean[d];
    float fm_cur  = g_framemean[DD + d];
    float m = fm_cur - fm_prev;
    g_mommean[d] = m;
    for (int i = 1; i < NM1; i++) {
        fm_prev = fm_cur;
        fm_cur = g_framemean[(i + 1) * DD + d];
        float diff = fm_cur - fm_prev;
        m = 0.5f * diff + 0.5f * m;
        g_mommean[i * DD + d] = m;
    }
}

// ---------------------------------------------------------------------------
// Split-K fp32 GEMM: part[z] = A[M,K-chunk] @ B[K-chunk,N]
// BM=32, BN=128, BK=32, 256 threads, 4x4 microtile, deterministic partials.
// ---------------------------------------------------------------------------
#define BM 32
#define BN 128
#define BK 32
__global__ void __launch_bounds__(256) gemm_splitk(
    const float* __restrict__ A, const float* __restrict__ B,
    float* __restrict__ Cpart, int M, int N, int K)
{
    __shared__ float As[BK][BM];
    __shared__ float Bs[BK][BN];
    int tid = threadIdx.x;
    int n0 = blockIdx.x * BN;
    int m0 = blockIdx.y * BM;
    int splitk = gridDim.z;
    int kchunk = K / splitk;
    int k0 = blockIdx.z * kchunk;
    int ksteps = kchunk / BK;

    int ty = tid >> 5;            // 0..7 -> rows ty*4..ty*4+3
    int tx = tid & 31;            // 0..31 -> cols tx*4..tx*4+3
    int a_m = tid >> 3;           // 0..31
    int a_k = (tid & 7) * 4;      // 0..28
    int b_r = tid >> 5;           // 0..7
    int b_c = (tid & 31) * 4;     // 0..124

    float acc[4][4] = {};

    for (int kt = 0; kt < ksteps; kt++) {
        int kbase = k0 + kt * BK;
        // load A tile (guard M)
        float4 av = make_float4(0.f, 0.f, 0.f, 0.f);
        int mg = m0 + a_m;
        if (mg < M) av = *(const float4*)&A[(size_t)mg * K + kbase + a_k];
        As[a_k + 0][a_m] = av.x;
        As[a_k + 1][a_m] = av.y;
        As[a_k + 2][a_m] = av.z;
        As[a_k + 3][a_m] = av.w;
        // load B tile
#pragma unroll
        for (int j = 0; j < 4; j++) {
            int kr = b_r + j * 8;
            *(float4*)&Bs[kr][b_c] =
                *(const float4*)&B[(size_t)(kbase + kr) * N + n0 + b_c];
        }
        __syncthreads();
#pragma unroll
        for (int kk = 0; kk < BK; kk++) {
            float4 a = *(const float4*)&As[kk][ty * 4];
            float4 b = *(const float4*)&Bs[kk][tx * 4];
            float ar[4] = {a.x, a.y, a.z, a.w};
            float br[4] = {b.x, b.y, b.z, b.w};
#pragma unroll
            for (int i = 0; i < 4; i++)
#pragma unroll
                for (int j = 0; j < 4; j++)
                    acc[i][j] = fmaf(ar[i], br[j], acc[i][j]);
        }
        __syncthreads();
    }

    size_t MN = (size_t)M * N;
    float* base = Cpart + (size_t)blockIdx.z * MN;
#pragma unroll
    for (int i = 0; i < 4; i++) {
        int mg = m0 + ty * 4 + i;
        if (mg < M) {
            float4 v = make_float4(acc[i][0], acc[i][1], acc[i][2], acc[i][3]);
            *(float4*)&base[(size_t)mg * N + n0 + tx * 4] = v;
        }
    }
}

// ---------------------------------------------------------------------------
// Combine split-K partials + bias (+ optional exact GELU)
// ---------------------------------------------------------------------------
__global__ void combine_kernel(const float* __restrict__ part,
                               const float* __restrict__ bias,
                               float* __restrict__ dst,
                               int M, int N, int splitk, int do_gelu)
{
    int idx = blockIdx.x * blockDim.x + threadIdx.x;
    int total = M * N;
    if (idx >= total) return;
    float v = bias[idx % N];
    size_t MN = (size_t)total;
    for (int z = 0; z < splitk; z++) v += part[(size_t)z * MN + idx];
    if (do_gelu) v = 0.5f * v * (1.0f + erff(v * 0.70710678118654752f));
    dst[idx] = v;
}

// ---------------------------------------------------------------------------
// LayerNorm over feat rows -> xn
// ---------------------------------------------------------------------------
__global__ void __launch_bounds__(256) ln_kernel(const float* __restrict__ ln_g,
                                                 const float* __restrict__ ln_b)
{
    int row = blockIdx.x;
    const float* x = g_feat + row * DD;
    float s = 0.f, ss = 0.f;
    for (int d = threadIdx.x; d < DD; d += 256) {
        float v = x[d];
        s += v;
        ss = fmaf(v, v, ss);
    }
    __shared__ float sh1[8], sh2[8];
    int lane = threadIdx.x & 31, w = threadIdx.x >> 5;
#pragma unroll
    for (int o = 16; o; o >>= 1) {
        s  += __shfl_xor_sync(0xFFFFFFFFu, s, o);
        ss += __shfl_xor_sync(0xFFFFFFFFu, ss, o);
    }
    if (lane == 0) { sh1[w] = s; sh2[w] = ss; }
    __syncthreads();
    if (w == 0) {
        s  = (lane < 8) ? sh1[lane] : 0.f;
        ss = (lane < 8) ? sh2[lane] : 0.f;
#pragma unroll
        for (int o = 4; o; o >>= 1) {
            s  += __shfl_xor_sync(0xFFFFFFFFu, s, o);
            ss += __shfl_xor_sync(0xFFFFFFFFu, ss, o);
        }
        if (lane == 0) { sh1[0] = s; sh2[0] = ss; }
    }
    __syncthreads();
    float mu  = sh1[0] * (1.0f / DD);
    float var = sh2[0] * (1.0f / DD) - mu * mu;
    float rstd = rsqrtf(var + 1e-5f);
    for (int d = threadIdx.x; d < DD; d += 256)
        g_xn[row * DD + d] = (x[d] - mu) * rstd * ln_g[d] + ln_b[d];
}

// ---------------------------------------------------------------------------
// Gate head: gate_logits = h @ W2 + b2 ; y = softmax((logits + g*0.1)/0.5)[1]
// grid 127, 64 threads (warp w handles output column w)
// ---------------------------------------------------------------------------
__global__ void __launch_bounds__(64) gate_kernel(const float* __restrict__ W2,
                                                  const float* __restrict__ b2,
                                                  const float* __restrict__ gu,
                                                  float* __restrict__ out)
{
    int row = blockIdx.x;
    int w = threadIdx.x >> 5, lane = threadIdx.x & 31;
    const float* hrow = g_h + row * DD;
    float s = 0.f;
    for (int d = lane; d < DD; d += 32)
        s = fmaf(hrow[d], W2[d * 2 + w], s);
#pragma unroll
    for (int o = 16; o; o >>= 1) s += __shfl_xor_sync(0xFFFFFFFFu, s, o);
    __shared__ float sl[2];
    if (lane == 0) sl[w] = s + b2[w];
    __syncthreads();
    if (threadIdx.x == 0) {
        float l0 = sl[0], l1 = sl[1];
        out[OUT_GATE + row * 2 + 0] = l0;
        out[OUT_GATE + row * 2 + 1] = l1;
        float u0 = gu[row * 2 + 0], u1 = gu[row * 2 + 1];
        float g0 = -logf(-logf(u0 + 1e-20f) + 1e-20f);
        float g1 = -logf(-logf(u1 + 1e-20f) + 1e-20f);
        float a0 = (l0 + g0 * 0.1f) * 2.0f;   // / TEMP(0.5)
        float a1 = (l1 + g1 * 0.1f) * 2.0f;
        float mx = fmaxf(a0, a1);
        float e0 = expf(a0 - mx), e1 = expf(a1 - mx);
        g_y[row] = e1 / (e0 + e1);
    }
}

// ---------------------------------------------------------------------------
// Top-8 selection (stable: max value, lowest index on ties), z_hard, weights
// ---------------------------------------------------------------------------
__global__ void __launch_bounds__(128) topk_kernel(float* __restrict__ out) {
    __shared__ float yv[128];
    __shared__ float rv[128];
    __shared__ int   ri[128];
    __shared__ int   taken[128];
    int t = threadIdx.x;
    yv[t] = (t < NM1) ? g_y[t] : -1e30f;
    taken[t] = 0;
    __syncthreads();
    for (int it = 0; it < NCUBES; it++) {
        rv[t] = taken[t] ? -1e30f : yv[t];
        ri[t] = t;
        __syncthreads();
        for (int off = 64; off > 0; off >>= 1) {
            if (t < off) {
                float v2 = rv[t + off]; int i2 = ri[t + off];
                if (v2 > rv[t] || (v2 == rv[t] && i2 < ri[t])) { rv[t] = v2; ri[t] = i2; }
            }
            __syncthreads();
        }
        if (t == 0) taken[ri[0]] = 1;
        __syncthreads();
    }
    // z_hard output (forward value of straight-through)
    float z = 0.f;
    if (t < NM1) z = taken[t] ? ((1.0f - yv[t]) + yv[t]) : 0.0f;
    if (t == 0) out[OUT_Z] = 1.0f;
    if (t < NM1) out[OUT_Z + 1 + t] = z;
    // sum z
    rv[t] = z;
    __syncthreads();
    for (int off = 64; off > 0; off >>= 1) {
        if (t < off) rv[t] += rv[t + off];
        __syncthreads();
    }
    if (t == 0) {
        float zsum = 1.0f + rv[0];
        g_scale = 1.0f / ((float)PG * zsum);
        g_selidx[0] = 0; g_selw[0] = 1.0f;
        int c = 1;
        for (int i = 0; i < NM1; i++) {
            if (taken[i]) {
                g_selidx[c] = i + 1;
                g_selw[c] = (1.0f - yv[i]) + yv[i];
                c++;
            }
        }
    }
}

// ---------------------------------------------------------------------------
// pooled[g][d] = scale * sum_k w_k * framepool[sel_k][g][d]
// ---------------------------------------------------------------------------
__global__ void __launch_bounds__(384) pooled_kernel() {
    int g = blockIdx.x;
    int d4 = threadIdx.x;
    float4 acc = make_float4(0.f, 0.f, 0.f, 0.f);
#pragma unroll
    for (int k = 0; k < PG; k++) {
        int n = g_selidx[k];
        float w = g_selw[k];
        float4 v = ((const float4*)(g_framepool + ((size_t)n * NQ + g) * DD))[d4];
        acc.x = fmaf(w, v.x, acc.x);
        acc.y = fmaf(w, v.y, acc.y);
        acc.z = fmaf(w, v.z, acc.z);
        acc.w = fmaf(w, v.w, acc.w);
    }
    float sc = g_scale;
    acc.x *= sc; acc.y *= sc; acc.z *= sc; acc.w *= sc;
    ((float4*)(g_pooled + g * DD))[d4] = acc;
}

// ---------------------------------------------------------------------------
// launch
// ---------------------------------------------------------------------------
extern "C" void kernel_launch(void* const* d_in, const int* in_sizes, int n_in,
                              void* d_out, int out_size) {
    const float* vf    = (const float*)d_in[0];
    const float* gu    = (const float*)d_in[1];
    const float* W_agg = (const float*)d_in[2];
    const float* b_agg = (const float*)d_in[3];
    const float* ln_g  = (const float*)d_in[4];
    const float* ln_b  = (const float*)d_in[5];
    const float* W1    = (const float*)d_in[6];
    const float* b1    = (const float*)d_in[7];
    const float* W2    = (const float*)d_in[8];
    const float* b2    = (const float*)d_in[9];
    const float* W_th  = (const float*)d_in[10];
    const float* b_th  = (const float*)d_in[11];
    float* out = (float*)d_out;

    float* d_part;   cudaGetSymbolAddress((void**)&d_part,   g_part);
    float* d_mom;    cudaGetSymbolAddress((void**)&d_mom,    g_mommean);
    float* d_feat;   cudaGetSymbolAddress((void**)&d_feat,   g_feat);
    float* d_xn;     cudaGetSymbolAddress((void**)&d_xn,     g_xn);
    float* d_h;      cudaGetSymbolAddress((void**)&d_h,      g_h);
    float* d_pooled; cudaGetSymbolAddress((void**)&d_pooled, g_pooled);

    // 1) stream video features once
    pool_kernel<<<dim3(NQ, NF), 384>>>(vf);
    // 2) frame means
    mean_kernel<<<NF, 384>>>();
    // 3) momentum EMA scan
    scan_kernel<<<4, 384>>>();
    // 4) feat = mommean @ W_agg + b_agg   (split-K=4)
    gemm_splitk<<<dim3(DD / BN, (NM1 + BM - 1) / BM, 4), 256>>>(d_mom, W_agg, d_part, NM1, DD, DD);
    combine_kernel<<<(NM1 * DD + 255) / 256, 256>>>(d_part, b_agg, d_feat, NM1, DD, 4, 0);
    // 5) LayerNorm
    ln_kernel<<<NM1, 256>>>(ln_g, ln_b);
    // 6) h = gelu(xn @ W1 + b1)
    gemm_splitk<<<dim3(DD / BN, (NM1 + BM - 1) / BM, 4), 256>>>(d_xn, W1, d_part, NM1, DD, DD);
    combine_kernel<<<(NM1 * DD + 255) / 256, 256>>>(d_part, b1, d_h, NM1, DD, 4, 1);
    // 7) gate logits + gumbel softmax y
    gate_kernel<<<NM1, 64>>>(W2, b2, gu, out);
    // 8) top-8 + z_hard
    topk_kernel<<<1, 128>>>(out);
    // 9) pooled from framepool (selected frames only)
    pooled_kernel<<<NQ, 384>>>();
    // 10) thumbnail = pooled @ W_th + b_th
    gemm_splitk<<<dim3(LM / BN, NQ / BM, 4), 256>>>(d_pooled, W_th, d_part, NQ, LM, DD);
    combine_kernel<<<(NQ * LM + 255) / 256, 256>>>(d_part, b_th, out + OUT_TH, NQ, LM, 4, 0);
}